// round 3
// baseline (speedup 1.0000x reference)
#include <cuda_runtime.h>

#define B_      1024
#define T_      8192
#define NW_     2048
#define NTH     512
#define NSTAGE  4
#define NCHUNK  2048          // chunks of 4 elems per row

__device__ float4       g_part[B_];
__device__ unsigned int g_count = 0;

__device__ __forceinline__ float wsumf(float v) {
#pragma unroll
    for (int o = 16; o > 0; o >>= 1) v += __shfl_down_sync(0xffffffffu, v, o);
    return v;
}
__device__ __forceinline__ double wsumd(double v) {
#pragma unroll
    for (int o = 16; o > 0; o >>= 1) v += __shfl_down_sync(0xffffffffu, v, o);
    return v;
}

__global__ void __launch_bounds__(NTH, 2) duration_loss_fused(
    const float* __restrict__ dur_pred,
    const float* __restrict__ dur_gt,
    const int*   __restrict__ ph2word,
    const int*   __restrict__ txt_tokens,
    float* __restrict__ out)
{
    __shared__ float2 s_tab[151];
    __shared__ float  s_wp[NW_], s_wg[NW_];
    __shared__ float  s_hp[NCHUNK], s_hg[NCHUNK];
    __shared__ int    s_hm[NCHUNK];
    __shared__ float  s_red[5][NTH / 32];
    __shared__ double s_dred[4][NTH / 32];
    __shared__ int    s_islast;

    const int tid  = threadIdx.x;
    const int lane = tid & 31;
    const int wid  = tid >> 5;
    const int b    = blockIdx.x;

    // token rule table: {expected_or_inf, is_ratio}
    for (int i = tid; i < 151; i += NTH) {
        float ex = 1e30f, rt = 0.0f;
        if (i == 94 || i == 100 || i == 92) ex = 2.0f;
        else if (i == 122)                  ex = 3.0f;
        else if (i == 43 || i == 27)        ex = 5.0f;
        if (i == 44 || i == 28 || i == 29 || i == 27 || i == 121 || i == 43) rt = 1.0f;
        s_tab[i] = make_float2(ex, rt);
    }
    for (int i = tid; i < NW_; i += NTH) { s_wp[i] = 0.0f; s_wg[i] = 0.0f; }
    __syncthreads();

    const float* dpr = dur_pred   + (size_t)b * T_;
    const float* gtr = dur_gt     + (size_t)b * T_;
    const int*   wr  = ph2word    + (size_t)b * T_;
    const int*   tkr = txt_tokens + (size_t)b * T_;

    float accR = 0.0f, accP = 0.0f, sp = 0.0f, sg = 0.0f;
    int   defw[NSTAGE];
    float defp[NSTAGE], defg[NSTAGE];
#pragma unroll
    for (int s = 0; s < NSTAGE; ++s) { defw[s] = -1; defp[s] = 0.0f; defg[s] = 0.0f; }

#pragma unroll
    for (int s = 0; s < NSTAGE; ++s) {
        const int j0 = s * (NTH * 4) + (tid << 2);

        const float4 dp4 = *reinterpret_cast<const float4*>(dpr + j0);
        const float4 gt4 = *reinterpret_cast<const float4*>(gtr + j0);
        const int4   tk4 = *reinterpret_cast<const int4*>(tkr + j0);
        const int4   w4  = *reinterpret_cast<const int4*>(wr  + j0);

        int wprev = -1, wnext = -1;
        if (j0 > 0)      wprev = wr[j0 - 1];
        if (j0 + 4 < T_) wnext = wr[j0 + 4];

        // dp[j0+4] for all lanes: shuffle of neighbor's dp4.x; lane31 loads.
        float dpn0 = __shfl_down_sync(0xffffffffu, dp4.x, 1);
        float dpn1l = 1e30f; int tknl = 150;
        if (lane == 31) {
            if (j0 + 4 < T_) {
                dpn0  = dpr[j0 + 4];
                dpn1l = dpr[j0 + 5];
                tknl  = tkr[j0 + 4];
            } else {
                dpn0 = 1e30f;
            }
        }

        // per-element gap terms (computed once; neighbor's via shuffle of g0)
        const float2 tb0 = s_tab[tk4.x];
        const float2 tb1 = s_tab[tk4.y];
        const float2 tb2 = s_tab[tk4.z];
        const float2 tb3 = s_tab[tk4.w];

        const float g1_0 = fmaxf(dp4.x - tb0.x, 0.0f);
        const float g2_0 = fmaxf(dp4.x - dp4.y * (1.0f/3.0f), 0.0f) * tb0.y;
        const float gE0  = g1_0 + g2_0;
        const float sa0  = (g2_0 > 0.0f) ? g2_0 : g1_0;

        float gE4 = __shfl_down_sync(0xffffffffu, gE0, 1);

        const float g1_1 = fmaxf(dp4.y - tb1.x, 0.0f);
        const float g2_1 = fmaxf(dp4.y - dp4.z * (1.0f/3.0f), 0.0f) * tb1.y;
        const float gE1  = g1_1 + g2_1;
        const float sa1  = (g2_1 > 0.0f) ? g2_1 : g1_1;

        const float g1_2 = fmaxf(dp4.z - tb2.x, 0.0f);
        const float g2_2 = fmaxf(dp4.z - dp4.w * (1.0f/3.0f), 0.0f) * tb2.y;
        const float gE2  = g1_2 + g2_2;
        const float sa2  = (g2_2 > 0.0f) ? g2_2 : g1_2;

        const float g1_3 = fmaxf(dp4.w - tb3.x, 0.0f);
        const float g2_3 = fmaxf(dp4.w - dpn0 * (1.0f/3.0f), 0.0f) * tb3.y;
        const float gE3  = g1_3 + g2_3;
        const float sa3  = (g2_3 > 0.0f) ? g2_3 : g1_3;

        if (lane == 31) {
            const float2 tbn = s_tab[tknl];
            const float a = fmaxf(dpn0 - tbn.x, 0.0f);
            const float c = fmaxf(dpn0 - dpn1l * (1.0f/3.0f), 0.0f) * tbn.y;
            gE4 = a + c;
        }

        // pointwise losses
        {
            const float la0 = __log2f(dp4.x + 1.0f);
            const float la1 = __log2f(dp4.y + 1.0f);
            const float la2 = __log2f(dp4.z + 1.0f);
            const float la3 = __log2f(dp4.w + 1.0f);
            const float r0 = dp4.x - sa0 + gE1;
            const float r1 = dp4.y - sa1 + gE2;
            const float r2 = dp4.z - sa2 + gE3;
            const float r3 = dp4.w - sa3 + gE4;
            const float d0 = la0 - __log2f(r0 + 1.0f);
            const float d1 = la1 - __log2f(r1 + 1.0f);
            const float d2 = la2 - __log2f(r2 + 1.0f);
            const float d3 = la3 - __log2f(r3 + 1.0f);
            accR = fmaf(d0, d0, accR); accR = fmaf(d1, d1, accR);
            accR = fmaf(d2, d2, accR); accR = fmaf(d3, d3, accR);
            const float q0 = la0 - __log2f(gt4.x + 1.0f);
            const float q1 = la1 - __log2f(gt4.y + 1.0f);
            const float q2 = la2 - __log2f(gt4.z + 1.0f);
            const float q3 = la3 - __log2f(gt4.w + 1.0f);
            accP = fmaf(q0, q0, accP); accP = fmaf(q1, q1, accP);
            accP = fmaf(q2, q2, accP); accP = fmaf(q3, q3, accP);
        }

        // ---- branch-free word-segment bookkeeping ----
        const float cp0 = fmaxf(dp4.x, 0.0f);
        const float cp1 = fmaxf(dp4.y, 0.0f);
        const float cp2 = fmaxf(dp4.z, 0.0f);
        const float cp3 = fmaxf(dp4.w, 0.0f);
        sp += (cp0 + cp1) + (cp2 + cp3);
        sg += (gt4.x + gt4.y) + (gt4.z + gt4.w);

        const float Sp3 = cp3,            Sg3 = gt4.w;
        const float Sp2 = cp2 + Sp3,      Sg2 = gt4.z + Sg3;
        const float Sp1 = cp1 + Sp2,      Sg1 = gt4.y + Sg2;
        const float Sp0 = cp0 + Sp1,      Sg0 = gt4.x + Sg1;

        const bool bb0 = (w4.x != wprev);
        const bool bb1 = (w4.y != w4.x);
        const bool bb2 = (w4.z != w4.y);
        const bool bb3 = (w4.w != w4.z);
        const bool bb4 = (wnext != w4.w);

        // suffix at next boundary after k (0 if none)
        const float SpN2 = bb3 ? Sp3 : 0.0f,  SgN2 = bb3 ? Sg3 : 0.0f;
        const float SpN1 = bb2 ? Sp2 : SpN2,  SgN1 = bb2 ? Sg2 : SgN2;
        const float SpN0 = bb1 ? Sp1 : SpN1,  SgN0 = bb1 ? Sg1 : SgN1;

        // run-reaches-chunk-end flags
        const bool t2 = !bb3;
        const bool t1 = t2 && !bb2;
        const bool t0 = t1 && !bb1;

        const int c = s * NTH + tid;
        s_hp[c] = Sp0 - SpN0;
        s_hg[c] = Sg0 - SgN0;
        s_hm[c] = w4.x | (t0 ? (int)0x80000000 : 0);

        if (bb0 && (!t0 || bb4)) { s_wp[w4.x] = Sp0 - SpN0; s_wg[w4.x] = Sg0 - SgN0; }
        if (bb1 && (!t1 || bb4)) { s_wp[w4.y] = Sp1 - SpN1; s_wg[w4.y] = Sg1 - SgN1; }
        if (bb2 && (!t2 || bb4)) { s_wp[w4.z] = Sp2 - SpN2; s_wg[w4.z] = Sg2 - SgN2; }
        if (bb3 && bb4)          { s_wp[w4.w] = Sp3;        s_wg[w4.w] = Sg3; }

        if (!bb4) {   // tail run continues into next chunk: defer (at most one start matches)
            if (bb3)            { defw[s] = w4.w; defp[s] = Sp3; defg[s] = Sg3; }
            else if (bb2 && t2) { defw[s] = w4.z; defp[s] = Sp2; defg[s] = Sg2; }
            else if (bb1 && t1) { defw[s] = w4.y; defp[s] = Sp1; defg[s] = Sg1; }
            else if (bb0 && t0) { defw[s] = w4.x; defp[s] = Sp0; defg[s] = Sg0; }
        }
    }
    __syncthreads();

    // resolve words spanning chunk boundaries (owner walks head-run chain)
#pragma unroll
    for (int s = 0; s < NSTAGE; ++s) {
        if (defw[s] >= 0) {
            const int w = defw[s];
            float p = defp[s], q = defg[s];
            int ci = s * NTH + tid + 1;
            while (ci < NCHUNK) {
                const int m = s_hm[ci];
                if ((m & 0x7fffffff) != w) break;
                p += s_hp[ci]; q += s_hg[ci];
                if (m >= 0) break;   // head run not full -> word ends here
                ++ci;
            }
            s_wp[w] = p; s_wg[w] = q;
        }
    }
    __syncthreads();

    // word-level loss (empty words give 0, word 0 excluded)
    float accW = 0.0f;
#pragma unroll
    for (int r = 0; r < NW_ / NTH; ++r) {
        const int w = r * NTH + tid;
        if (w > 0) {
            const float d = __log2f(s_wp[w] + 1.0f) - __log2f(s_wg[w] + 1.0f);
            accW = fmaf(d, d, accW);
        }
    }

    // block reduction -> per-block partial
    float v[5] = { accR, accP, accW, sp, sg };
#pragma unroll
    for (int q = 0; q < 5; ++q) {
        const float r = wsumf(v[q]);
        if (lane == 0) s_red[q][wid] = r;
    }
    __syncthreads();
    if (wid == 0) {
        float t[5];
#pragma unroll
        for (int q = 0; q < 5; ++q) {
            float x = (lane < NTH / 32) ? s_red[q][lane] : 0.0f;
            t[q] = wsumf(x);
        }
        if (lane == 0) {
            const float ds = __log2f(t[3] + 1.0f) - __log2f(t[4] + 1.0f);
            g_part[b] = make_float4(t[0], t[1], t[2], ds * ds);
            __threadfence();
            const unsigned tk = atomicAdd(&g_count, 1u);
            s_islast = (tk == (unsigned)(gridDim.x - 1));
        }
    }
    __syncthreads();

    if (s_islast) {
        __threadfence();
        double a0 = 0.0, a1 = 0.0, a2 = 0.0, a3 = 0.0;
        for (int i = tid; i < B_; i += NTH) {
            const float4 p = g_part[i];
            a0 += p.x; a1 += p.y; a2 += p.z; a3 += p.w;
        }
        double dv[4] = { a0, a1, a2, a3 };
#pragma unroll
        for (int q = 0; q < 4; ++q) {
            const double r = wsumd(dv[q]);
            if (lane == 0) s_dred[q][wid] = r;
        }
        __syncthreads();
        if (wid == 0) {
            double t[4];
#pragma unroll
            for (int q = 0; q < 4; ++q) {
                double x = (lane < NTH / 32) ? s_dred[q][lane] : 0.0;
                t[q] = wsumd(x);
            }
            if (lane == 0) {
                const double LN2SQ = 0.4804530139182014;   // ln(2)^2
                const double loss = LN2SQ * ((0.3 * t[0] + 0.6 * t[1]) / 8388608.0
                                           + 0.3 * t[2] / 2096128.0
                                           + 0.1 * t[3] / 1024.0);
                out[0] = (float)loss;
                g_count = 0;   // reset for next graph replay
            }
        }
    }
}

extern "C" void kernel_launch(void* const* d_in, const int* in_sizes, int n_in,
                              void* d_out, int out_size) {
    const float* dur_pred   = (const float*)d_in[0];
    const float* dur_gt     = (const float*)d_in[1];
    const int*   ph2word    = (const int*)d_in[2];
    const int*   txt_tokens = (const int*)d_in[3];
    duration_loss_fused<<<B_, NTH>>>(dur_pred, dur_gt, ph2word, txt_tokens, (float*)d_out);
}